// round 6
// baseline (speedup 1.0000x reference)
#include <cuda_runtime.h>
#include <cuda_bf16.h>
#include <cstdint>

// Problem constants (fixed by the dataset)
#define NN 50000
#define EE 400000
#define HH 2
#define DD 128
#define HD 256          // HH*DD
#define ET 450000       // EE + NN (self loops appended)
#define NEG_SLOPE 0.2f
#define NB 196          // (NN + 255) / 256 scan blocks

// ---------------- scratch (static device memory; no allocation allowed) ----
__device__ float g_xl[(size_t)NN * HD];
__device__ float g_xr[(size_t)NN * HD];
__device__ float g_agg[(size_t)NN * HD];
__device__ int   g_src[ET];
__device__ int   g_dst[ET];
__device__ int   g_deg[NN];        // histogram, then reused as scatter cursor
__device__ int   g_off[NN + 1];
__device__ int   g_csr_src[ET];
__device__ int   g_bsum[256];
__device__ int   g_boff[256];
__device__ float g_bias_eff[DD];
__device__ int   g_is64;

// ---------------- helpers --------------------------------------------------
__device__ __forceinline__ float lrelu(float v) {
    return v > 0.f ? v : NEG_SLOPE * v;
}
__device__ __forceinline__ uint32_t f2tf32(float f) {
    uint32_t u;
    asm("cvt.rna.tf32.f32 %0, %1;" : "=r"(u) : "f"(f));
    return u;
}
__device__ __forceinline__ void mma_tf32(float c[4], const uint32_t a[4],
                                         const uint32_t b[2]) {
    asm volatile(
        "mma.sync.aligned.m16n8k8.row.col.f32.tf32.tf32.f32 "
        "{%0,%1,%2,%3}, {%4,%5,%6,%7}, {%8,%9}, {%0,%1,%2,%3};"
        : "+f"(c[0]), "+f"(c[1]), "+f"(c[2]), "+f"(c[3])
        : "r"(a[0]), "r"(a[1]), "r"(a[2]), "r"(a[3]), "r"(b[0]), "r"(b[1]));
}
#define CP_ASYNC16(dst_smem, src_ptr) \
    asm volatile("cp.async.ca.shared.global [%0], [%1], 16;" \
                 :: "r"(dst_smem), "l"(src_ptr))
#define CP_COMMIT() asm volatile("cp.async.commit_group;")
#define CP_WAIT2()  asm volatile("cp.async.wait_group 2;")
#define CP_WAIT1()  asm volatile("cp.async.wait_group 1;")
#define CP_WAIT0()  asm volatile("cp.async.wait_group 0;")

// ---------------- edge prep -------------------------------------------------
__global__ void detect_dtype_kernel(const unsigned* __restrict__ w) {
    unsigned v = w[2 * threadIdx.x + 1];
    int any = __syncthreads_or(v != 0u);
    if (threadIdx.x == 0) g_is64 = (any == 0) ? 1 : 0;
}
__global__ void zero_deg_kernel() {
    int i = blockIdx.x * blockDim.x + threadIdx.x;
    if (i < NN) g_deg[i] = 0;
}
// convert + histogram fused
__global__ void convert_hist_kernel(const void* __restrict__ ei) {
    int e = blockIdx.x * blockDim.x + threadIdx.x;
    if (e >= ET) return;
    int s, d;
    if (e < EE) {
        if (g_is64) {
            const long long* p = (const long long*)ei;
            s = (int)p[e];
            d = (int)p[EE + e];
        } else {
            const int* p = (const int*)ei;
            s = p[e];
            d = p[EE + e];
        }
    } else {
        s = e - EE;   // self loop
        d = e - EE;
    }
    g_src[e] = s;
    g_dst[e] = d;
    atomicAdd(&g_deg[d], 1);
}

// ---------------- multi-block exclusive scan of g_deg -> g_off -------------
__global__ __launch_bounds__(256)
void scan_p1_kernel() {
    __shared__ int sh[256];
    int i = blockIdx.x * 256 + threadIdx.x;
    sh[threadIdx.x] = (i < NN) ? g_deg[i] : 0;
    __syncthreads();
    for (int o = 128; o; o >>= 1) {
        if (threadIdx.x < o) sh[threadIdx.x] += sh[threadIdx.x + o];
        __syncthreads();
    }
    if (threadIdx.x == 0) g_bsum[blockIdx.x] = sh[0];
}
__global__ __launch_bounds__(256)
void scan_p2_kernel() {
    __shared__ int sh[256];
    int tid = threadIdx.x;
    int v = (tid < NB) ? g_bsum[tid] : 0;
    sh[tid] = v;
    __syncthreads();
    for (int o = 1; o < 256; o <<= 1) {
        int t = (tid >= o) ? sh[tid - o] : 0;
        __syncthreads();
        sh[tid] += t;
        __syncthreads();
    }
    if (tid < NB) g_boff[tid] = sh[tid] - v;   // exclusive block offsets
    if (tid == 255) g_off[NN] = sh[255];       // total
}
__global__ __launch_bounds__(256)
void scan_p3_kernel() {
    __shared__ int sh[256];
    int tid = threadIdx.x;
    int i = blockIdx.x * 256 + tid;
    int v = (i < NN) ? g_deg[i] : 0;
    sh[tid] = v;
    __syncthreads();
    for (int o = 1; o < 256; o <<= 1) {
        int t = (tid >= o) ? sh[tid - o] : 0;
        __syncthreads();
        sh[tid] += t;
        __syncthreads();
    }
    if (i < NN) {
        g_off[i] = g_boff[blockIdx.x] + sh[tid] - v;
        g_deg[i] = 0;   // reuse as scatter cursor
    }
}
__global__ void scatter_kernel() {
    int e = blockIdx.x * blockDim.x + threadIdx.x;
    if (e >= ET) return;
    int d = g_dst[e];
    int pos = atomicAdd(&g_deg[d], 1);
    g_csr_src[g_off[d] + pos] = g_src[e];
}

// ---------------- bias fold: bias_eff = bo + bias_conv @ Wo^T --------------
__global__ void biaseff_kernel(const float* __restrict__ bias_conv,
                               const float* __restrict__ Wo,
                               const float* __restrict__ bo) {
    int c = threadIdx.x;
    if (c >= DD) return;
    float s = bo[c];
    for (int k = 0; k < HD; k++) s += bias_conv[k] * Wo[(size_t)c * HD + k];
    g_bias_eff[c] = s;
}

// ---------------- TF32 GEMM, dual weight/output sets, 3-stage cp.async -----
// For blockIdx.y < ycnt: C0[M,OUT] = A @ W0^T + b0 (col block = y)
// else:                  C1[M,OUT] = A @ W1^T + b1 (col block = y - ycnt)
#define SMS 20
#define STG (128 * SMS)                 // floats per stage per operand
#define GEMM_SMEM (2 * 3 * STG * 4)     // bytes: A+B, 3 stages
__global__ __launch_bounds__(256, 2)
void tf32_gemm_kernel(const float* __restrict__ A,
                      const float* __restrict__ W0, const float* __restrict__ b0v,
                      float* __restrict__ C0,
                      const float* __restrict__ W1, const float* __restrict__ b1v,
                      float* __restrict__ C1,
                      int M, int K, int OUT, int ycnt) {
    extern __shared__ float smem_dyn[];
    float* As = smem_dyn;               // [3][STG]
    float* Bs = smem_dyn + 3 * STG;     // [3][STG]

    const float* W;  const float* bias;  float* C;
    int yb = blockIdx.y;
    if (yb < ycnt) { W = W0; bias = b0v; C = C0; }
    else           { W = W1; bias = b1v; C = C1; yb -= ycnt; }

    const int tid  = threadIdx.x;
    const int lane = tid & 31;
    const int wid  = tid >> 5;
    const int warpM = wid & 1;
    const int warpN = wid >> 1;
    const int gp = lane >> 2;
    const int tg = lane & 3;
    const int rowBlock = blockIdx.x * 128;
    const int colBlock = yb * 128;
    const int lr = tid >> 2;          // 0..63
    const int lc = (tid & 3) * 4;     // 0/4/8/12

    float acc[4][4][4];
#pragma unroll
    for (int mt = 0; mt < 4; mt++)
#pragma unroll
        for (int nt = 0; nt < 4; nt++)
#pragma unroll
            for (int r = 0; r < 4; r++) acc[mt][nt][r] = 0.f;

    auto load_stage = [&](int k0, int buf) {
#pragma unroll
        for (int h = 0; h < 2; h++) {
            int row  = lr + h * 64;
            int grow = rowBlock + row;
            float* sa = &As[buf * STG + row * SMS + lc];
            if (grow < M) {
                CP_ASYNC16((uint32_t)__cvta_generic_to_shared(sa),
                           A + (size_t)grow * K + k0 + lc);
            } else {
                sa[0] = 0.f; sa[1] = 0.f; sa[2] = 0.f; sa[3] = 0.f;
            }
            float* sb = &Bs[buf * STG + row * SMS + lc];
            CP_ASYNC16((uint32_t)__cvta_generic_to_shared(sb),
                       W + (size_t)(colBlock + row) * K + k0 + lc);
        }
    };

    const int nk = K >> 4;              // >= 8 always here
    load_stage(0, 0);
    CP_COMMIT();
    load_stage(16, 1);
    CP_COMMIT();

    for (int t = 0; t < nk; t++) {
        int cur = t % 3;
        if (t + 2 < nk) {
            load_stage((t + 2) << 4, (t + 2) % 3);
            CP_COMMIT();
            CP_WAIT2();
        } else if (t + 1 < nk) {
            CP_WAIT1();
        } else {
            CP_WAIT0();
        }
        __syncthreads();

#pragma unroll
        for (int kk = 0; kk < 16; kk += 8) {
            uint32_t af[4][4], bf[4][2];
#pragma unroll
            for (int mt = 0; mt < 4; mt++) {
                int m0 = warpM * 64 + mt * 16;
                af[mt][0] = f2tf32(As[cur * STG + (m0 + gp)     * SMS + kk + tg]);
                af[mt][1] = f2tf32(As[cur * STG + (m0 + gp + 8) * SMS + kk + tg]);
                af[mt][2] = f2tf32(As[cur * STG + (m0 + gp)     * SMS + kk + tg + 4]);
                af[mt][3] = f2tf32(As[cur * STG + (m0 + gp + 8) * SMS + kk + tg + 4]);
            }
#pragma unroll
            for (int nt = 0; nt < 4; nt++) {
                int n0 = warpN * 32 + nt * 8;
                bf[nt][0] = f2tf32(Bs[cur * STG + (n0 + gp) * SMS + kk + tg]);
                bf[nt][1] = f2tf32(Bs[cur * STG + (n0 + gp) * SMS + kk + tg + 4]);
            }
#pragma unroll
            for (int mt = 0; mt < 4; mt++)
#pragma unroll
                for (int nt = 0; nt < 4; nt++)
                    mma_tf32(acc[mt][nt], af[mt], bf[nt]);
        }
        __syncthreads();
    }

    // epilogue
#pragma unroll
    for (int mt = 0; mt < 4; mt++) {
#pragma unroll
        for (int nt = 0; nt < 4; nt++) {
            int col  = colBlock + warpN * 32 + nt * 8 + tg * 2;
            float bb0 = bias[col], bb1 = bias[col + 1];
            int row0 = rowBlock + warpM * 64 + mt * 16 + gp;
            if (row0 < M) {
                float2 o = make_float2(acc[mt][nt][0] + bb0, acc[mt][nt][1] + bb1);
                *(float2*)(C + (size_t)row0 * OUT + col) = o;
            }
            int row1 = row0 + 8;
            if (row1 < M) {
                float2 o = make_float2(acc[mt][nt][2] + bb0, acc[mt][nt][3] + bb1);
                *(float2*)(C + (size_t)row1 * OUT + col) = o;
            }
        }
    }
}

// ---------------- fused GAT pass: one warp per destination node -------------
// lanes 0-15 = head 0, lanes 16-31 = head 1; each lane owns 8 feature cols.
// 4-slot rolling register prefetch of neighbor tiles (steady-state MLP ~8).
__global__ __launch_bounds__(256)
void gat_fused_kernel(const float* __restrict__ att) {
    int n = (blockIdx.x * blockDim.x + threadIdx.x) >> 5;
    int lane = threadIdx.x & 31;
    if (n >= NN) return;
    int off = lane * 8;

    const float4* pr = (const float4*)(g_xr + (size_t)n * HD + off);
    float4 b0 = pr[0], b1 = pr[1];
    float4 v0 = *(const float4*)(att + off);
    float4 v1 = *(const float4*)(att + off + 4);

    float acc[8] = {0, 0, 0, 0, 0, 0, 0, 0};
    float denom = 0.f;

    const int beg = g_off[n], end = g_off[n + 1];
    const int m = end - beg;

    auto edge_compute = [&](float4 c0, float4 c1) {
        float t = lrelu(c0.x + b0.x) * v0.x + lrelu(c0.y + b0.y) * v0.y +
                  lrelu(c0.z + b0.z) * v0.z + lrelu(c0.w + b0.w) * v0.w +
                  lrelu(c1.x + b1.x) * v1.x + lrelu(c1.y + b1.y) * v1.y +
                  lrelu(c1.z + b1.z) * v1.z + lrelu(c1.w + b1.w) * v1.w;
#pragma unroll
        for (int o = 8; o; o >>= 1) t += __shfl_xor_sync(0xFFFFFFFFu, t, o);
        float ex = __expf(fminf(t, 80.f));
        acc[0] = fmaf(ex, c0.x, acc[0]);
        acc[1] = fmaf(ex, c0.y, acc[1]);
        acc[2] = fmaf(ex, c0.z, acc[2]);
        acc[3] = fmaf(ex, c0.w, acc[3]);
        acc[4] = fmaf(ex, c1.x, acc[4]);
        acc[5] = fmaf(ex, c1.y, acc[5]);
        acc[6] = fmaf(ex, c1.z, acc[6]);
        acc[7] = fmaf(ex, c1.w, acc[7]);
        denom += ex;
    };

    float4 p0[4], p1[4];
#pragma unroll
    for (int k = 0; k < 4; k++) {
        if (k < m) {
            int s = g_csr_src[beg + k];
            const float4* p = (const float4*)(g_xl + (size_t)s * HD + off);
            p0[k] = p[0]; p1[k] = p[1];
        }
    }

    int i = beg;
    for (; i + 4 <= end; i += 4) {
#pragma unroll
        for (int k = 0; k < 4; k++) {
            float4 c0 = p0[k], c1 = p1[k];
            if (i + 4 + k < end) {
                int sn = g_csr_src[i + 4 + k];
                const float4* pn = (const float4*)(g_xl + (size_t)sn * HD + off);
                p0[k] = pn[0]; p1[k] = pn[1];
            }
            edge_compute(c0, c1);
        }
    }
    int r = end - i;                     // 0..3 remaining, in slots 0..r-1
    if (r > 0) edge_compute(p0[0], p1[0]);
    if (r > 1) edge_compute(p0[1], p1[1]);
    if (r > 2) edge_compute(p0[2], p1[2]);

    float inv = 1.f / (denom + 1e-16f);
    float4 o0 = make_float4(acc[0] * inv, acc[1] * inv, acc[2] * inv, acc[3] * inv);
    float4 o1 = make_float4(acc[4] * inv, acc[5] * inv, acc[6] * inv, acc[7] * inv);
    float4* po = (float4*)(g_agg + (size_t)n * HD + off);
    po[0] = o0;
    po[1] = o1;
}

// ---------------- launch ---------------------------------------------------
extern "C" void kernel_launch(void* const* d_in, const int* in_sizes, int n_in,
                              void* d_out, int out_size) {
    const float* x         = (const float*)d_in[0];
    const void*  edge      = d_in[1];
    const float* Wl        = (const float*)d_in[2];
    const float* bl        = (const float*)d_in[3];
    const float* Wr        = (const float*)d_in[4];
    const float* br        = (const float*)d_in[5];
    const float* att       = (const float*)d_in[6];
    const float* bias_conv = (const float*)d_in[7];
    const float* Wo        = (const float*)d_in[8];
    const float* bo        = (const float*)d_in[9];
    float* out = (float*)d_out;

    float* xl;   cudaGetSymbolAddress((void**)&xl,   g_xl);
    float* xr;   cudaGetSymbolAddress((void**)&xr,   g_xr);
    float* agg;  cudaGetSymbolAddress((void**)&agg,  g_agg);
    float* beff; cudaGetSymbolAddress((void**)&beff, g_bias_eff);

    // opt-in dynamic smem for the 3-stage GEMM (idempotent)
    cudaFuncSetAttribute(tf32_gemm_kernel,
                         cudaFuncAttributeMaxDynamicSharedMemorySize, GEMM_SMEM);

    // One-time side stream + events (no device-memory allocation involved).
    static cudaStream_t s_side = nullptr;
    static cudaEvent_t  s_fork = nullptr, s_join = nullptr;
    if (!s_side) {
        cudaStreamCreateWithFlags(&s_side, cudaStreamNonBlocking);
        cudaEventCreateWithFlags(&s_fork, cudaEventDisableTiming);
        cudaEventCreateWithFlags(&s_join, cudaEventDisableTiming);
    }

    // -------- fork: projections (side) || CSR build (main) --------
    cudaEventRecord(s_fork, 0);
    cudaStreamWaitEvent(s_side, s_fork, 0);

    // side stream: bias fold + node projections (xl, xr)
    biaseff_kernel<<<1, 128, 0, s_side>>>(bias_conv, Wo, bo);
    {
        dim3 grid((NN + 127) / 128, 4);
        tf32_gemm_kernel<<<grid, 256, GEMM_SMEM, s_side>>>(
            x, Wl, bl, xl, Wr, br, xr, NN, DD, HD, 2);
    }

    // main stream: edges -> int32 (+self loops) + histogram -> scan -> CSR
    detect_dtype_kernel<<<1, 256>>>((const unsigned*)edge);
    zero_deg_kernel<<<(NN + 255) / 256, 256>>>();
    convert_hist_kernel<<<(ET + 255) / 256, 256>>>(edge);
    scan_p1_kernel<<<NB, 256>>>();
    scan_p2_kernel<<<1, 256>>>();
    scan_p3_kernel<<<NB, 256>>>();
    scatter_kernel<<<(ET + 255) / 256, 256>>>();

    // -------- join --------
    cudaEventRecord(s_join, s_side);
    cudaStreamWaitEvent(0, s_join, 0);

    // fused: score -> exp -> weighted aggregate (one warp per node)
    gat_fused_kernel<<<(NN * 32 + 255) / 256, 256>>>(att);

    // output projection: out = agg @ Wo^T + bias_eff
    {
        dim3 grid((NN + 127) / 128, 1);
        tf32_gemm_kernel<<<grid, 256, GEMM_SMEM>>>(
            agg, Wo, beff, out, Wo, beff, out, NN, HD, DD, 1);
    }
}

// round 7
// speedup vs baseline: 1.0050x; 1.0050x over previous
#include <cuda_runtime.h>
#include <cuda_bf16.h>
#include <cstdint>

// Problem constants (fixed by the dataset)
#define NN 50000
#define EE 400000
#define HH 2
#define DD 128
#define HD 256          // HH*DD
#define ET 450000       // EE + NN (self loops appended)
#define NEG_SLOPE 0.2f
#define NB 196          // (NN + 255) / 256 scan blocks

// ---------------- scratch (static device memory; no allocation allowed) ----
__device__ float g_xl[(size_t)NN * HD];
__device__ float g_xr[(size_t)NN * HD];
__device__ float g_agg[(size_t)NN * HD];
__device__ int   g_src[ET];
__device__ int   g_dst[ET];
__device__ int   g_deg[NN];        // histogram, then reused as scatter cursor
__device__ int   g_off[NN + 1];
__device__ int   g_csr_src[ET];
__device__ int   g_bsum[256];
__device__ int   g_boff[256];
__device__ float g_bias_eff[DD];
__device__ int   g_is64;

// ---------------- helpers --------------------------------------------------
__device__ __forceinline__ float lrelu(float v) {
    return v > 0.f ? v : NEG_SLOPE * v;
}
__device__ __forceinline__ uint32_t f2tf32(float f) {
    uint32_t u;
    asm("cvt.rna.tf32.f32 %0, %1;" : "=r"(u) : "f"(f));
    return u;
}
__device__ __forceinline__ void mma_tf32(float c[4], const uint32_t a[4],
                                         const uint32_t b[2]) {
    asm volatile(
        "mma.sync.aligned.m16n8k8.row.col.f32.tf32.tf32.f32 "
        "{%0,%1,%2,%3}, {%4,%5,%6,%7}, {%8,%9}, {%0,%1,%2,%3};"
        : "+f"(c[0]), "+f"(c[1]), "+f"(c[2]), "+f"(c[3])
        : "r"(a[0]), "r"(a[1]), "r"(a[2]), "r"(a[3]), "r"(b[0]), "r"(b[1]));
}
#define CP_ASYNC16(dst_smem, src_ptr) \
    asm volatile("cp.async.ca.shared.global [%0], [%1], 16;" \
                 :: "r"(dst_smem), "l"(src_ptr))
#define CP_COMMIT() asm volatile("cp.async.commit_group;")
#define CP_WAIT2()  asm volatile("cp.async.wait_group 2;")
#define CP_WAIT1()  asm volatile("cp.async.wait_group 1;")
#define CP_WAIT0()  asm volatile("cp.async.wait_group 0;")

// ---------------- edge prep -------------------------------------------------
__global__ void detect_dtype_kernel(const unsigned* __restrict__ w) {
    unsigned v = w[2 * threadIdx.x + 1];
    int any = __syncthreads_or(v != 0u);
    if (threadIdx.x == 0) g_is64 = (any == 0) ? 1 : 0;
}
__global__ void zero_deg_kernel() {
    int i = blockIdx.x * blockDim.x + threadIdx.x;
    if (i < NN) g_deg[i] = 0;
}
// convert + histogram fused
__global__ void convert_hist_kernel(const void* __restrict__ ei) {
    int e = blockIdx.x * blockDim.x + threadIdx.x;
    if (e >= ET) return;
    int s, d;
    if (e < EE) {
        if (g_is64) {
            const long long* p = (const long long*)ei;
            s = (int)p[e];
            d = (int)p[EE + e];
        } else {
            const int* p = (const int*)ei;
            s = p[e];
            d = p[EE + e];
        }
    } else {
        s = e - EE;   // self loop
        d = e - EE;
    }
    g_src[e] = s;
    g_dst[e] = d;
    atomicAdd(&g_deg[d], 1);
}

// ---------------- multi-block exclusive scan of g_deg -> g_off -------------
__global__ __launch_bounds__(256)
void scan_p1_kernel() {
    __shared__ int sh[256];
    int i = blockIdx.x * 256 + threadIdx.x;
    sh[threadIdx.x] = (i < NN) ? g_deg[i] : 0;
    __syncthreads();
    for (int o = 128; o; o >>= 1) {
        if (threadIdx.x < o) sh[threadIdx.x] += sh[threadIdx.x + o];
        __syncthreads();
    }
    if (threadIdx.x == 0) g_bsum[blockIdx.x] = sh[0];
}
__global__ __launch_bounds__(256)
void scan_p2_kernel() {
    __shared__ int sh[256];
    int tid = threadIdx.x;
    int v = (tid < NB) ? g_bsum[tid] : 0;
    sh[tid] = v;
    __syncthreads();
    for (int o = 1; o < 256; o <<= 1) {
        int t = (tid >= o) ? sh[tid - o] : 0;
        __syncthreads();
        sh[tid] += t;
        __syncthreads();
    }
    if (tid < NB) g_boff[tid] = sh[tid] - v;   // exclusive block offsets
    if (tid == 255) g_off[NN] = sh[255];       // total
}
__global__ __launch_bounds__(256)
void scan_p3_kernel() {
    __shared__ int sh[256];
    int tid = threadIdx.x;
    int i = blockIdx.x * 256 + tid;
    int v = (i < NN) ? g_deg[i] : 0;
    sh[tid] = v;
    __syncthreads();
    for (int o = 1; o < 256; o <<= 1) {
        int t = (tid >= o) ? sh[tid - o] : 0;
        __syncthreads();
        sh[tid] += t;
        __syncthreads();
    }
    if (i < NN) {
        g_off[i] = g_boff[blockIdx.x] + sh[tid] - v;
        g_deg[i] = 0;   // reuse as scatter cursor
    }
}
__global__ void scatter_kernel() {
    int e = blockIdx.x * blockDim.x + threadIdx.x;
    if (e >= ET) return;
    int d = g_dst[e];
    int pos = atomicAdd(&g_deg[d], 1);
    g_csr_src[g_off[d] + pos] = g_src[e];
}

// ---------------- bias fold: bias_eff = bo + bias_conv @ Wo^T --------------
__global__ void biaseff_kernel(const float* __restrict__ bias_conv,
                               const float* __restrict__ Wo,
                               const float* __restrict__ bo) {
    int c = threadIdx.x;
    if (c >= DD) return;
    float s = bo[c];
    for (int k = 0; k < HD; k++) s += bias_conv[k] * Wo[(size_t)c * HD + k];
    g_bias_eff[c] = s;
}

// ---------------- TF32 GEMM, dual weight/output sets, 3-stage cp.async -----
// For blockIdx.y < ycnt: C0[M,OUT] = A @ W0^T + b0 (col block = y)
// else:                  C1[M,OUT] = A @ W1^T + b1 (col block = y - ycnt)
#define SMS 20
#define STG (128 * SMS)                 // floats per stage per operand
#define GEMM_SMEM (2 * 3 * STG * 4)     // bytes: A+B, 3 stages
__global__ __launch_bounds__(256, 2)
void tf32_gemm_kernel(const float* __restrict__ A,
                      const float* __restrict__ W0, const float* __restrict__ b0v,
                      float* __restrict__ C0,
                      const float* __restrict__ W1, const float* __restrict__ b1v,
                      float* __restrict__ C1,
                      int M, int K, int OUT, int ycnt) {
    extern __shared__ float smem_dyn[];
    float* As = smem_dyn;               // [3][STG]
    float* Bs = smem_dyn + 3 * STG;     // [3][STG]

    const float* W;  const float* bias;  float* C;
    int yb = blockIdx.y;
    if (yb < ycnt) { W = W0; bias = b0v; C = C0; }
    else           { W = W1; bias = b1v; C = C1; yb -= ycnt; }

    const int tid  = threadIdx.x;
    const int lane = tid & 31;
    const int wid  = tid >> 5;
    const int warpM = wid & 1;
    const int warpN = wid >> 1;
    const int gp = lane >> 2;
    const int tg = lane & 3;
    const int rowBlock = blockIdx.x * 128;
    const int colBlock = yb * 128;
    const int lr = tid >> 2;          // 0..63
    const int lc = (tid & 3) * 4;     // 0/4/8/12

    float acc[4][4][4];
#pragma unroll
    for (int mt = 0; mt < 4; mt++)
#pragma unroll
        for (int nt = 0; nt < 4; nt++)
#pragma unroll
            for (int r = 0; r < 4; r++) acc[mt][nt][r] = 0.f;

    auto load_stage = [&](int k0, int buf) {
#pragma unroll
        for (int h = 0; h < 2; h++) {
            int row  = lr + h * 64;
            int grow = rowBlock + row;
            float* sa = &As[buf * STG + row * SMS + lc];
            if (grow < M) {
                CP_ASYNC16((uint32_t)__cvta_generic_to_shared(sa),
                           A + (size_t)grow * K + k0 + lc);
            } else {
                sa[0] = 0.f; sa[1] = 0.f; sa[2] = 0.f; sa[3] = 0.f;
            }
            float* sb = &Bs[buf * STG + row * SMS + lc];
            CP_ASYNC16((uint32_t)__cvta_generic_to_shared(sb),
                       W + (size_t)(colBlock + row) * K + k0 + lc);
        }
    };

    const int nk = K >> 4;              // >= 8 always here
    load_stage(0, 0);
    CP_COMMIT();
    load_stage(16, 1);
    CP_COMMIT();

    for (int t = 0; t < nk; t++) {
        int cur = t % 3;
        if (t + 2 < nk) {
            load_stage((t + 2) << 4, (t + 2) % 3);
            CP_COMMIT();
            CP_WAIT2();
        } else if (t + 1 < nk) {
            CP_WAIT1();
        } else {
            CP_WAIT0();
        }
        __syncthreads();

#pragma unroll
        for (int kk = 0; kk < 16; kk += 8) {
            uint32_t af[4][4], bf[4][2];
#pragma unroll
            for (int mt = 0; mt < 4; mt++) {
                int m0 = warpM * 64 + mt * 16;
                af[mt][0] = f2tf32(As[cur * STG + (m0 + gp)     * SMS + kk + tg]);
                af[mt][1] = f2tf32(As[cur * STG + (m0 + gp + 8) * SMS + kk + tg]);
                af[mt][2] = f2tf32(As[cur * STG + (m0 + gp)     * SMS + kk + tg + 4]);
                af[mt][3] = f2tf32(As[cur * STG + (m0 + gp + 8) * SMS + kk + tg + 4]);
            }
#pragma unroll
            for (int nt = 0; nt < 4; nt++) {
                int n0 = warpN * 32 + nt * 8;
                bf[nt][0] = f2tf32(Bs[cur * STG + (n0 + gp) * SMS + kk + tg]);
                bf[nt][1] = f2tf32(Bs[cur * STG + (n0 + gp) * SMS + kk + tg + 4]);
            }
#pragma unroll
            for (int mt = 0; mt < 4; mt++)
#pragma unroll
                for (int nt = 0; nt < 4; nt++)
                    mma_tf32(acc[mt][nt], af[mt], bf[nt]);
        }
        __syncthreads();
    }

    // epilogue
#pragma unroll
    for (int mt = 0; mt < 4; mt++) {
#pragma unroll
        for (int nt = 0; nt < 4; nt++) {
            int col  = colBlock + warpN * 32 + nt * 8 + tg * 2;
            float bb0 = bias[col], bb1 = bias[col + 1];
            int row0 = rowBlock + warpM * 64 + mt * 16 + gp;
            if (row0 < M) {
                float2 o = make_float2(acc[mt][nt][0] + bb0, acc[mt][nt][1] + bb1);
                *(float2*)(C + (size_t)row0 * OUT + col) = o;
            }
            int row1 = row0 + 8;
            if (row1 < M) {
                float2 o = make_float2(acc[mt][nt][2] + bb0, acc[mt][nt][3] + bb1);
                *(float2*)(C + (size_t)row1 * OUT + col) = o;
            }
        }
    }
}

// ---------------- fused GAT pass: one warp per destination node -------------
// lanes 0-15 = head 0, lanes 16-31 = head 1; each lane owns 8 feature cols.
// 4-slot rolling register prefetch of neighbor tiles (steady-state MLP ~8).
__global__ __launch_bounds__(256)
void gat_fused_kernel(const float* __restrict__ att) {
    int n = (blockIdx.x * blockDim.x + threadIdx.x) >> 5;
    int lane = threadIdx.x & 31;
    if (n >= NN) return;
    int off = lane * 8;

    const float4* pr = (const float4*)(g_xr + (size_t)n * HD + off);
    float4 b0 = pr[0], b1 = pr[1];
    float4 v0 = *(const float4*)(att + off);
    float4 v1 = *(const float4*)(att + off + 4);

    float acc[8] = {0, 0, 0, 0, 0, 0, 0, 0};
    float denom = 0.f;

    const int beg = g_off[n], end = g_off[n + 1];
    const int m = end - beg;

    auto edge_compute = [&](float4 c0, float4 c1) {
        float t = lrelu(c0.x + b0.x) * v0.x + lrelu(c0.y + b0.y) * v0.y +
                  lrelu(c0.z + b0.z) * v0.z + lrelu(c0.w + b0.w) * v0.w +
                  lrelu(c1.x + b1.x) * v1.x + lrelu(c1.y + b1.y) * v1.y +
                  lrelu(c1.z + b1.z) * v1.z + lrelu(c1.w + b1.w) * v1.w;
#pragma unroll
        for (int o = 8; o; o >>= 1) t += __shfl_xor_sync(0xFFFFFFFFu, t, o);
        float ex = __expf(fminf(t, 80.f));
        acc[0] = fmaf(ex, c0.x, acc[0]);
        acc[1] = fmaf(ex, c0.y, acc[1]);
        acc[2] = fmaf(ex, c0.z, acc[2]);
        acc[3] = fmaf(ex, c0.w, acc[3]);
        acc[4] = fmaf(ex, c1.x, acc[4]);
        acc[5] = fmaf(ex, c1.y, acc[5]);
        acc[6] = fmaf(ex, c1.z, acc[6]);
        acc[7] = fmaf(ex, c1.w, acc[7]);
        denom += ex;
    };

    float4 p0[4], p1[4];
#pragma unroll
    for (int k = 0; k < 4; k++) {
        if (k < m) {
            int s = g_csr_src[beg + k];
            const float4* p = (const float4*)(g_xl + (size_t)s * HD + off);
            p0[k] = p[0]; p1[k] = p[1];
        }
    }

    int i = beg;
    for (; i + 4 <= end; i += 4) {
#pragma unroll
        for (int k = 0; k < 4; k++) {
            float4 c0 = p0[k], c1 = p1[k];
            if (i + 4 + k < end) {
                int sn = g_csr_src[i + 4 + k];
                const float4* pn = (const float4*)(g_xl + (size_t)sn * HD + off);
                p0[k] = pn[0]; p1[k] = pn[1];
            }
            edge_compute(c0, c1);
        }
    }
    int r = end - i;                     // 0..3 remaining, in slots 0..r-1
    if (r > 0) edge_compute(p0[0], p1[0]);
    if (r > 1) edge_compute(p0[1], p1[1]);
    if (r > 2) edge_compute(p0[2], p1[2]);

    float inv = 1.f / (denom + 1e-16f);
    float4 o0 = make_float4(acc[0] * inv, acc[1] * inv, acc[2] * inv, acc[3] * inv);
    float4 o1 = make_float4(acc[4] * inv, acc[5] * inv, acc[6] * inv, acc[7] * inv);
    float4* po = (float4*)(g_agg + (size_t)n * HD + off);
    po[0] = o0;
    po[1] = o1;
}

// ---------------- launch ---------------------------------------------------
extern "C" void kernel_launch(void* const* d_in, const int* in_sizes, int n_in,
                              void* d_out, int out_size) {
    const float* x         = (const float*)d_in[0];
    const void*  edge      = d_in[1];
    const float* Wl        = (const float*)d_in[2];
    const float* bl        = (const float*)d_in[3];
    const float* Wr        = (const float*)d_in[4];
    const float* br        = (const float*)d_in[5];
    const float* att       = (const float*)d_in[6];
    const float* bias_conv = (const float*)d_in[7];
    const float* Wo        = (const float*)d_in[8];
    const float* bo        = (const float*)d_in[9];
    float* out = (float*)d_out;

    float* xl;   cudaGetSymbolAddress((void**)&xl,   g_xl);
    float* xr;   cudaGetSymbolAddress((void**)&xr,   g_xr);
    float* agg;  cudaGetSymbolAddress((void**)&agg,  g_agg);
    float* beff; cudaGetSymbolAddress((void**)&beff, g_bias_eff);

    // opt-in dynamic smem for the 3-stage GEMM (idempotent)
    cudaFuncSetAttribute(tf32_gemm_kernel,
                         cudaFuncAttributeMaxDynamicSharedMemorySize, GEMM_SMEM);

    // One-time side stream + events (no device-memory allocation involved).
    static cudaStream_t s_side = nullptr;
    static cudaEvent_t  s_fork = nullptr, s_join = nullptr;
    if (!s_side) {
        cudaStreamCreateWithFlags(&s_side, cudaStreamNonBlocking);
        cudaEventCreateWithFlags(&s_fork, cudaEventDisableTiming);
        cudaEventCreateWithFlags(&s_join, cudaEventDisableTiming);
    }

    // -------- fork: projections (side) || CSR build (main) --------
    cudaEventRecord(s_fork, 0);
    cudaStreamWaitEvent(s_side, s_fork, 0);

    // side stream: bias fold + node projections (xl, xr)
    biaseff_kernel<<<1, 128, 0, s_side>>>(bias_conv, Wo, bo);
    {
        dim3 grid((NN + 127) / 128, 4);
        tf32_gemm_kernel<<<grid, 256, GEMM_SMEM, s_side>>>(
            x, Wl, bl, xl, Wr, br, xr, NN, DD, HD, 2);
    }

    // main stream: edges -> int32 (+self loops) + histogram -> scan -> CSR
    detect_dtype_kernel<<<1, 256>>>((const unsigned*)edge);
    zero_deg_kernel<<<(NN + 255) / 256, 256>>>();
    convert_hist_kernel<<<(ET + 255) / 256, 256>>>(edge);
    scan_p1_kernel<<<NB, 256>>>();
    scan_p2_kernel<<<1, 256>>>();
    scan_p3_kernel<<<NB, 256>>>();
    scatter_kernel<<<(ET + 255) / 256, 256>>>();

    // -------- join --------
    cudaEventRecord(s_join, s_side);
    cudaStreamWaitEvent(0, s_join, 0);

    // fused: score -> exp -> weighted aggregate (one warp per node)
    gat_fused_kernel<<<(NN * 32 + 255) / 256, 256>>>(att);

    // output projection: out = agg @ Wo^T + bias_eff
    {
        dim3 grid((NN + 127) / 128, 1);
        tf32_gemm_kernel<<<grid, 256, GEMM_SMEM>>>(
            agg, Wo, beff, out, Wo, beff, out, NN, HD, DD, 1);
    }
}